// round 12
// baseline (speedup 1.0000x reference)
#include <cuda_runtime.h>
#include <cuda_bf16.h>
#include <cstdint>
#include <mma.h>

using namespace nvcuda;
typedef __nv_bfloat16 bf16;

#define NN 100000
#define NNPAD 100096   // 782 * 128
#define EE 1600000
#define INDIM 64
#define HDDIM 128

// ---------------- scratch (static device globals; no allocation) ----------------
__device__ float g_maskx[NN * INDIM];
__device__ float g_feat [NNPAD * HDDIM];
__device__ float g_el   [NN * 2];
__device__ float g_er   [NN * 2];
__device__ float g_h0   [NN * HDDIM];
__device__ float g_h1   [NN * HDDIM];
__device__ float g_rep0 [NNPAD * INDIM];
__device__ float g_r0   [NN * HDDIM];
__device__ float g_accb [NN * HDDIM];
__device__ int   g_ptr  [NN + 1];
__device__ int   g_cnt  [NN];      // zero at load; every call leaves it zero
__device__ int   g_csrc [EE];
__device__ int   g_rflag[NN];      // bit i = node remasked in decoder iteration i

// ---------------- CSR build ----------------
__global__ void hist_kernel(const int* __restrict__ dst) {
    int i = blockIdx.x * blockDim.x + threadIdx.x;
    if (i < EE) atomicAdd(&g_cnt[dst[i]], 1);
}

__global__ void scan_kernel() {
    const int T = 1024;
    const int CH = (NN + T - 1) / T;
    __shared__ int ss[T];
    int t = threadIdx.x;
    int lo = t * CH;
    int hi = lo + CH; if (hi > NN) hi = NN;
    int s = 0;
    for (int i = lo; i < hi; i++) s += g_cnt[i];
    ss[t] = s;
    __syncthreads();
    for (int off = 1; off < T; off <<= 1) {
        int v = (t >= off) ? ss[t - off] : 0;
        __syncthreads();
        ss[t] += v;
        __syncthreads();
    }
    int run = (t == 0) ? 0 : ss[t - 1];
    for (int i = lo; i < hi; i++) { g_ptr[i] = run; run += g_cnt[i]; g_cnt[i] = 0; }
    if (t == 0) g_ptr[NN] = ss[T - 1];
}

__global__ void scatter_kernel(const int* __restrict__ src, const int* __restrict__ dst) {
    int i = blockIdx.x * blockDim.x + threadIdx.x;
    if (i < EE) {
        int d = dst[i];
        int off = atomicAdd(&g_cnt[d], 1);
        g_csrc[g_ptr[d] + off] = src[i];
    }
}

__global__ void zero_cnt_kernel() {
    int i = blockIdx.x * blockDim.x + threadIdx.x;
    if (i < NN) g_cnt[i] = 0;
}

// ---------------- row masking ----------------
__global__ void set_rows_kernel(float* __restrict__ buf, const int* __restrict__ idx,
                                int cnt, const float* __restrict__ token) {
    int i = blockIdx.x * blockDim.x + threadIdx.x;
    if (i < cnt * INDIM) {
        int r = idx[i >> 6];
        buf[r * INDIM + (i & 63)] = token[i & 63];
    }
}

// ---------------- decoder remask flags ----------------
__global__ void zero_rflag_kernel() {
    int i = blockIdx.x * blockDim.x + threadIdx.x;
    if (i < NN) g_rflag[i] = 0;
}

__global__ void set_rflag_kernel(const int* __restrict__ remask, int remaskCnt) {
    int i = blockIdx.x * blockDim.x + threadIdx.x;
    if (i < 3 * remaskCnt) {
        int iter = i / remaskCnt;
        atomicOr(&g_rflag[remask[i]], 1 << iter);
    }
}

// ---------------- bf16 split helper: v = hi + lo + O(2^-18 v) ----------------
__device__ __forceinline__ void split_bf16(float v, bf16& h, bf16& l) {
    h = __float2bfloat16_rn(v);
    l = __float2bfloat16_rn(v - __bfloat162float(h));
}

// ---------------- tensor-core GEMM via bf16 3-term split (~fp32 accuracy) ----------------
template <int K, int BN, bool HAS_A2, bool REMASK, bool GUARD>
__global__ __launch_bounds__(256) void gemm_bf16_kernel(
    const float* __restrict__ A, const float* __restrict__ A2, float scaleA,
    const float* __restrict__ W, float* __restrict__ outF,
    const float* __restrict__ token, int iter)
{
    constexpr int BM = 128, KB = 32;
    constexpr int ASTR = KB + 8;
    constexpr int WSTR = BN + 8;
    constexpr int WYC = (BN == 128) ? 2 : 4;
    constexpr int WXC = 8 / WYC;
    constexpr int WM = BM / WYC;
    constexpr int WN = BN / WXC;
    constexpr int AR = WM / 16;
    constexpr int AC = WN / 16;

    constexpr int AS_ELEMS = BM * ASTR;
    constexpr int WS_ELEMS = KB * WSTR;
    constexpr int MAIN_BYTES  = (2 * AS_ELEMS + 2 * WS_ELEMS) * 2;
    constexpr int STAGE_BYTES = GUARD ? BM * BN * 4 : 0;
    constexpr int SM_BYTES    = MAIN_BYTES > STAGE_BYTES ? MAIN_BYTES : STAGE_BYTES;

    __shared__ __align__(32) char sraw[SM_BYTES];
    bf16* AsH = (bf16*)sraw;
    bf16* AsL = AsH + AS_ELEMS;
    bf16* WsH = AsL + AS_ELEMS;
    bf16* WsL = WsH + WS_ELEMS;

    int tid = threadIdx.x;
    int wid = tid >> 5;
    int wy = wid / WXC;
    int wx = wid % WXC;
    long n0 = (long)blockIdx.x * BM;

    wmma::fragment<wmma::accumulator, 16, 16, 16, float> acc[AR][AC];
#pragma unroll
    for (int r = 0; r < AR; r++)
#pragma unroll
        for (int c = 0; c < AC; c++)
            wmma::fill_fragment(acc[r][c], 0.0f);

    for (int kb = 0; kb < K; kb += KB) {
#pragma unroll
        for (int it = 0; it < 4; it++) {
            int f4  = tid + it * 256;
            int row = f4 >> 3;
            int c4  = f4 & 7;
            long n  = n0 + row;
            float4 v = make_float4(0.f, 0.f, 0.f, 0.f);
            if (n < NN) {
                if (REMASK && ((g_rflag[n] >> iter) & 1)) {
                    v = *(const float4*)(token + kb + 4 * c4);
                } else {
                    v = *(const float4*)(A + n * K + kb + 4 * c4);
                    if (HAS_A2) {
                        float4 v2 = *(const float4*)(A2 + n * K + kb + 4 * c4);
                        v.x += v2.x; v.y += v2.y; v.z += v2.z; v.w += v2.w;
                    }
                    v.x *= scaleA; v.y *= scaleA; v.z *= scaleA; v.w *= scaleA;
                }
            }
            bf16 h0, l0, h1, l1, h2, l2, h3, l3;
            split_bf16(v.x, h0, l0);
            split_bf16(v.y, h1, l1);
            split_bf16(v.z, h2, l2);
            split_bf16(v.w, h3, l3);
            int off = row * ASTR + 4 * c4;
            __nv_bfloat162 p;
            p.x = h0; p.y = h1; *(__nv_bfloat162*)&AsH[off]     = p;
            p.x = h2; p.y = h3; *(__nv_bfloat162*)&AsH[off + 2] = p;
            p.x = l0; p.y = l1; *(__nv_bfloat162*)&AsL[off]     = p;
            p.x = l2; p.y = l3; *(__nv_bfloat162*)&AsL[off + 2] = p;
        }
#pragma unroll
        for (int it = 0; it < KB * (BN / 4) / 256; it++) {
            int f4  = tid + it * 256;
            int row = f4 / (BN / 4);
            int c4  = f4 % (BN / 4);
            float4 v = *(const float4*)(W + (long)(kb + row) * BN + 4 * c4);
            bf16 h0, l0, h1, l1, h2, l2, h3, l3;
            split_bf16(v.x, h0, l0);
            split_bf16(v.y, h1, l1);
            split_bf16(v.z, h2, l2);
            split_bf16(v.w, h3, l3);
            int off = row * WSTR + 4 * c4;
            __nv_bfloat162 p;
            p.x = h0; p.y = h1; *(__nv_bfloat162*)&WsH[off]     = p;
            p.x = h2; p.y = h3; *(__nv_bfloat162*)&WsH[off + 2] = p;
            p.x = l0; p.y = l1; *(__nv_bfloat162*)&WsL[off]     = p;
            p.x = l2; p.y = l3; *(__nv_bfloat162*)&WsL[off + 2] = p;
        }
        __syncthreads();

#pragma unroll
        for (int ks = 0; ks < 2; ks++) {
            wmma::fragment<wmma::matrix_b, 16, 16, 16, bf16, wmma::row_major> bH[AC], bL[AC];
#pragma unroll
            for (int c = 0; c < AC; c++) {
                wmma::load_matrix_sync(bH[c], WsH + (ks * 16) * WSTR + wx * WN + c * 16, WSTR);
                wmma::load_matrix_sync(bL[c], WsL + (ks * 16) * WSTR + wx * WN + c * 16, WSTR);
            }
#pragma unroll
            for (int r = 0; r < AR; r++) {
                wmma::fragment<wmma::matrix_a, 16, 16, 16, bf16, wmma::row_major> aH, aL;
                wmma::load_matrix_sync(aH, AsH + (wy * WM + r * 16) * ASTR + ks * 16, ASTR);
                wmma::load_matrix_sync(aL, AsL + (wy * WM + r * 16) * ASTR + ks * 16, ASTR);
#pragma unroll
                for (int c = 0; c < AC; c++) {
                    wmma::mma_sync(acc[r][c], aH, bH[c], acc[r][c]);
                    wmma::mma_sync(acc[r][c], aH, bL[c], acc[r][c]);
                    wmma::mma_sync(acc[r][c], aL, bH[c], acc[r][c]);
                }
            }
        }
        __syncthreads();
    }

    if (!GUARD) {
#pragma unroll
        for (int r = 0; r < AR; r++)
#pragma unroll
            for (int c = 0; c < AC; c++)
                wmma::store_matrix_sync(outF + (n0 + wy * WM + r * 16) * BN + wx * WN + c * 16,
                                        acc[r][c], BN, wmma::mem_row_major);
    } else {
        float* stage = (float*)sraw;
#pragma unroll
        for (int r = 0; r < AR; r++)
#pragma unroll
            for (int c = 0; c < AC; c++)
                wmma::store_matrix_sync(stage + (wy * WM + r * 16) * BN + wx * WN + c * 16,
                                        acc[r][c], BN, wmma::mem_row_major);
        __syncthreads();
#pragma unroll
        for (int it = 0; it < BM * (BN / 4) / 256; it++) {
            int f4  = tid + it * 256;
            int row = f4 / (BN / 4);
            int c4  = f4 % (BN / 4);
            long n  = n0 + row;
            if (n < NN)
                *(float4*)(outF + n * BN + 4 * c4) = *(float4*)(stage + row * BN + 4 * c4);
        }
    }
}

// ---------------- el/er: per-node attention logits from feat ----------------
__global__ __launch_bounds__(256) void elr_kernel(
    const float* __restrict__ feat, const float* __restrict__ al, const float* __restrict__ ar,
    float* __restrict__ el, float* __restrict__ er)
{
    int warp = (blockIdx.x * blockDim.x + threadIdx.x) >> 5;
    if (warp >= NN) return;
    int lane = threadIdx.x & 31;

    float4 f  = *(const float4*)(feat + (long)warp * HDDIM + 4 * lane);
    float4 a4 = *(const float4*)(al + 4 * lane);
    float4 r4 = *(const float4*)(ar + 4 * lane);
    float ep = f.x * a4.x + f.y * a4.y + f.z * a4.z + f.w * a4.w;
    float rp = f.x * r4.x + f.y * r4.y + f.z * r4.z + f.w * r4.w;
#pragma unroll
    for (int off = 8; off; off >>= 1) {
        ep += __shfl_down_sync(0xffffffffu, ep, off, 16);
        rp += __shfl_down_sync(0xffffffffu, rp, off, 16);
    }
    if ((lane & 15) == 0) {
        el[2 * warp + (lane >> 4)] = ep;
        er[2 * warp + (lane >> 4)] = rp;
    }
}

// ---------------- attention: warp per node; edge softmax + weighted gather (MLP-4) + bias + ELU ----------------
__global__ __launch_bounds__(256) void attn_kernel(
    const float* __restrict__ feat, const float* __restrict__ el, const float* __restrict__ er,
    const float* __restrict__ bias, float* __restrict__ out, int accumulate)
{
    int warp = (blockIdx.x * blockDim.x + threadIdx.x) >> 5;
    if (warp >= NN) return;
    int lane = threadIdx.x & 31;

    int s = g_ptr[warp], e = g_ptr[warp + 1];
    float er0 = er[2 * warp], er1 = er[2 * warp + 1];

    // pass 1: online softmax stats
    float m0 = -1e30f, m1 = -1e30f, s0 = 0.f, s1 = 0.f;
    for (int i = s + lane; i < e; i += 32) {
        int sv = g_csrc[i];
        float2 ev = *(const float2*)(el + 2 * sv);
        float e0 = ev.x + er0; e0 = (e0 > 0.f) ? e0 : 0.2f * e0;
        float e1 = ev.y + er1; e1 = (e1 > 0.f) ? e1 : 0.2f * e1;
        float nm0 = fmaxf(m0, e0);
        s0 = s0 * __expf(m0 - nm0) + __expf(e0 - nm0);
        m0 = nm0;
        float nm1 = fmaxf(m1, e1);
        s1 = s1 * __expf(m1 - nm1) + __expf(e1 - nm1);
        m1 = nm1;
    }
#pragma unroll
    for (int off = 16; off; off >>= 1) {
        float om0 = __shfl_down_sync(0xffffffffu, m0, off);
        float os0 = __shfl_down_sync(0xffffffffu, s0, off);
        float nm0 = fmaxf(m0, om0);
        s0 = s0 * __expf(m0 - nm0) + os0 * __expf(om0 - nm0);
        m0 = nm0;
        float om1 = __shfl_down_sync(0xffffffffu, m1, off);
        float os1 = __shfl_down_sync(0xffffffffu, s1, off);
        float nm1 = fmaxf(m1, om1);
        s1 = s1 * __expf(m1 - nm1) + os1 * __expf(om1 - nm1);
        m1 = nm1;
    }
    m0 = __shfl_sync(0xffffffffu, m0, 0);
    s0 = __shfl_sync(0xffffffffu, s0, 0);
    m1 = __shfl_sync(0xffffffffu, m1, 0);
    s1 = __shfl_sync(0xffffffffu, s1, 0);
    float inv0 = 1.f / s0, inv1 = 1.f / s1;

    // pass 2: weighted gather, unrolled x4 for MLP; select head AFTER shuffle
    int colbase = 4 * lane;
    const bool head0 = (colbase < 64);
    const float* featc = feat + colbase;
    float4 acc = make_float4(0.f, 0.f, 0.f, 0.f);
    for (int base = s; base < e; base += 32) {
        int i = base + lane;
        float a0 = 0.f, a1 = 0.f;
        int sv = 0;
        if (i < e) {
            sv = g_csrc[i];
            float2 ev = *(const float2*)(el + 2 * sv);
            float e0 = ev.x + er0; e0 = (e0 > 0.f) ? e0 : 0.2f * e0;
            float e1 = ev.y + er1; e1 = (e1 > 0.f) ? e1 : 0.2f * e1;
            a0 = __expf(e0 - m0) * inv0;
            a1 = __expf(e1 - m1) * inv1;
        }
        int cnt = e - base; if (cnt > 32) cnt = 32;

        int j = 0;
        for (; j + 4 <= cnt; j += 4) {
            int s0j = __shfl_sync(0xffffffffu, sv, j);
            int s1j = __shfl_sync(0xffffffffu, sv, j + 1);
            int s2j = __shfl_sync(0xffffffffu, sv, j + 2);
            int s3j = __shfl_sync(0xffffffffu, sv, j + 3);
            float p00 = __shfl_sync(0xffffffffu, a0, j);
            float p01 = __shfl_sync(0xffffffffu, a1, j);
            float p10 = __shfl_sync(0xffffffffu, a0, j + 1);
            float p11 = __shfl_sync(0xffffffffu, a1, j + 1);
            float p20 = __shfl_sync(0xffffffffu, a0, j + 2);
            float p21 = __shfl_sync(0xffffffffu, a1, j + 2);
            float p30 = __shfl_sync(0xffffffffu, a0, j + 3);
            float p31 = __shfl_sync(0xffffffffu, a1, j + 3);
            float w0 = head0 ? p00 : p01;
            float w1 = head0 ? p10 : p11;
            float w2 = head0 ? p20 : p21;
            float w3 = head0 ? p30 : p31;
            float4 f0 = *(const float4*)(featc + (long)s0j * HDDIM);
            float4 f1 = *(const float4*)(featc + (long)s1j * HDDIM);
            float4 f2 = *(const float4*)(featc + (long)s2j * HDDIM);
            float4 f3 = *(const float4*)(featc + (long)s3j * HDDIM);
            acc.x += w0 * f0.x + w1 * f1.x + w2 * f2.x + w3 * f3.x;
            acc.y += w0 * f0.y + w1 * f1.y + w2 * f2.y + w3 * f3.y;
            acc.z += w0 * f0.z + w1 * f1.z + w2 * f2.z + w3 * f3.z;
            acc.w += w0 * f0.w + w1 * f1.w + w2 * f2.w + w3 * f3.w;
        }
        for (; j < cnt; j++) {
            int sj = __shfl_sync(0xffffffffu, sv, j);
            float q0 = __shfl_sync(0xffffffffu, a0, j);
            float q1 = __shfl_sync(0xffffffffu, a1, j);
            float wj = head0 ? q0 : q1;
            float4 f = *(const float4*)(featc + (long)sj * HDDIM);
            acc.x += wj * f.x;
            acc.y += wj * f.y;
            acc.z += wj * f.z;
            acc.w += wj * f.w;
        }
    }

    float4 bv = *(const float4*)(bias + colbase);
    float4 v;
    v.x = acc.x + bv.x; v.x = (v.x > 0.f) ? v.x : expm1f(v.x);
    v.y = acc.y + bv.y; v.y = (v.y > 0.f) ? v.y : expm1f(v.y);
    v.z = acc.z + bv.z; v.z = (v.z > 0.f) ? v.z : expm1f(v.z);
    v.w = acc.w + bv.w; v.w = (v.w > 0.f) ? v.w : expm1f(v.w);

    float* o = out + (long)warp * HDDIM + colbase;
    if (accumulate) {
        float4 p = *(const float4*)o;
        v.x += p.x; v.y += p.y; v.z += p.z; v.w += p.w;
    }
    *(float4*)o = v;
}

// ---------------- host ----------------
extern "C" void kernel_launch(void* const* d_in, const int* in_sizes, int n_in,
                              void* d_out, int out_size)
{
    const float* x        = (const float*)d_in[0];
    const int*   src      = (const int*)d_in[1];
    const int*   dst      = (const int*)d_in[2];
    const int*   encm     = (const int*)d_in[3];
    const int*   remask   = (const int*)d_in[4];
    const float* enc_fc0  = (const float*)d_in[5];
    const float* enc_al0  = (const float*)d_in[6];
    const float* enc_ar0  = (const float*)d_in[7];
    const float* enc_b0   = (const float*)d_in[8];
    const float* enc_fc1  = (const float*)d_in[9];
    const float* enc_al1  = (const float*)d_in[10];
    const float* enc_ar1  = (const float*)d_in[11];
    const float* enc_b1   = (const float*)d_in[12];
    const float* dec_fc0  = (const float*)d_in[13];
    const float* dec_al0  = (const float*)d_in[14];
    const float* dec_ar0  = (const float*)d_in[15];
    const float* dec_b0   = (const float*)d_in[16];
    const float* dec_fc1  = (const float*)d_in[17];
    const float* dec_al1  = (const float*)d_in[18];
    const float* dec_ar1  = (const float*)d_in[19];
    const float* dec_b1   = (const float*)d_in[20];
    const float* enc_tok  = (const float*)d_in[21];
    const float* dec_tok  = (const float*)d_in[22];
    const float* W_e2d    = (const float*)d_in[23];
    const float* W_d2c    = (const float*)d_in[24];
    float* out = (float*)d_out;

    int encCnt    = in_sizes[3];
    int remaskCnt = in_sizes[4] / 3;

    void *p_maskx, *p_feat, *p_el, *p_er, *p_h0, *p_h1, *p_rep0, *p_r0, *p_acc;
    cudaGetSymbolAddress(&p_maskx, g_maskx);
    cudaGetSymbolAddress(&p_feat,  g_feat);
    cudaGetSymbolAddress(&p_el,    g_el);
    cudaGetSymbolAddress(&p_er,    g_er);
    cudaGetSymbolAddress(&p_h0,    g_h0);
    cudaGetSymbolAddress(&p_h1,    g_h1);
    cudaGetSymbolAddress(&p_rep0,  g_rep0);
    cudaGetSymbolAddress(&p_r0,    g_r0);
    cudaGetSymbolAddress(&p_acc,   g_accb);

    float* maskx = (float*)p_maskx;
    float* feat  = (float*)p_feat;
    float* el    = (float*)p_el;
    float* er    = (float*)p_er;
    float* h0    = (float*)p_h0;
    float* h1    = (float*)p_h1;
    float* rep0  = (float*)p_rep0;
    float* r0    = (float*)p_r0;
    float* accb  = (float*)p_acc;

    const int EB  = (EE + 255) / 256;
    const int GTC = NNPAD / 128;
    const int AB  = (NN + 7) / 8;

    // ---- CSR build ----
    hist_kernel<<<EB, 256>>>(dst);
    scan_kernel<<<1, 1024>>>();
    scatter_kernel<<<EB, 256>>>(src, dst);

    // ---- encoder mask ----
    cudaMemcpyAsync(maskx, x, (size_t)NN * INDIM * sizeof(float), cudaMemcpyDeviceToDevice);
    set_rows_kernel<<<(encCnt * INDIM + 255) / 256, 256>>>(maskx, encm, encCnt, enc_tok);

    // ---- decoder remask flags ----
    zero_rflag_kernel<<<(NN + 255) / 256, 256>>>();
    set_rflag_kernel<<<(3 * remaskCnt + 255) / 256, 256>>>(remask, remaskCnt);

    // ---- encoder layer 0 ----
    gemm_bf16_kernel<INDIM, HDDIM, false, false, false><<<GTC, 256>>>(
        maskx, nullptr, 1.f, enc_fc0, feat, nullptr, 0);
    elr_kernel<<<AB, 256>>>(feat, enc_al0, enc_ar0, el, er);
    attn_kernel<<<AB, 256>>>(feat, el, er, enc_b0, h0, 0);

    // ---- encoder layer 1 ----
    gemm_bf16_kernel<HDDIM, HDDIM, false, false, false><<<GTC, 256>>>(
        h0, nullptr, 1.f, enc_fc1, feat, nullptr, 0);
    elr_kernel<<<AB, 256>>>(feat, enc_al1, enc_ar1, el, er);
    attn_kernel<<<AB, 256>>>(feat, el, er, enc_b1, h1, 0);

    // ---- Es = 0.5*(h0+h1); origin_rep = Es @ W_e2d ----
    gemm_bf16_kernel<HDDIM, INDIM, true, false, false><<<GTC, 256>>>(
        h0, h1, 0.5f, W_e2d, rep0, nullptr, 0);

    // ---- decoder x3, accumulate r1 into accb ----
    cudaMemsetAsync(p_acc, 0, (size_t)NN * HDDIM * sizeof(float));
    for (int i = 0; i < 3; i++) {
        gemm_bf16_kernel<INDIM, HDDIM, false, true, false><<<GTC, 256>>>(
            rep0, nullptr, 1.f, dec_fc0, feat, dec_tok, i);
        elr_kernel<<<AB, 256>>>(feat, dec_al0, dec_ar0, el, er);
        attn_kernel<<<AB, 256>>>(feat, el, er, dec_b0, r0, 0);

        gemm_bf16_kernel<HDDIM, HDDIM, false, false, false><<<GTC, 256>>>(
            r0, nullptr, 1.f, dec_fc1, feat, nullptr, 0);
        elr_kernel<<<AB, 256>>>(feat, dec_al1, dec_ar1, el, er);
        attn_kernel<<<AB, 256>>>(feat, el, er, dec_b1, accb, 1);
    }

    // ---- out = (accb/3) @ W_d2c ----
    gemm_bf16_kernel<HDDIM, INDIM, false, false, true><<<GTC, 256>>>(
        accb, nullptr, 1.f / 3.f, W_d2c, out, nullptr, 0);

    // ---- leave g_cnt zero for the next call ----
    zero_cnt_kernel<<<(NN + 255) / 256, 256>>>();
}

// round 15
// speedup vs baseline: 1.0489x; 1.0489x over previous
#include <cuda_runtime.h>
#include <cuda_bf16.h>
#include <cuda_fp16.h>
#include <cstdint>
#include <mma.h>

using namespace nvcuda;
typedef __nv_bfloat16 bf16;

#define NN 100000
#define NNPAD 100096   // 782 * 128
#define EE 1600000
#define INDIM 64
#define HDDIM 128

// ---------------- scratch (static device globals; no allocation) ----------------
__device__ float g_maskx[NN * INDIM];
__device__ float g_feat [NNPAD * HDDIM];
__device__ __half g_feath[NN * HDDIM];   // fp16 shadow of feat for the gather pass
__device__ float g_el   [NN * 2];
__device__ float g_er   [NN * 2];
__device__ float g_h0   [NN * HDDIM];
__device__ float g_h1   [NN * HDDIM];
__device__ float g_rep0 [NNPAD * INDIM];
__device__ float g_r0   [NN * HDDIM];
__device__ float g_accb [NN * HDDIM];
__device__ int   g_ptr  [NN + 1];
__device__ int   g_cnt  [NN];      // zero at load; every call leaves it zero
__device__ int   g_csrc [EE];
__device__ int   g_rflag[NN];      // bit i = node remasked in decoder iteration i

// ---------------- CSR build ----------------
__global__ void hist_kernel(const int* __restrict__ dst) {
    int i = blockIdx.x * blockDim.x + threadIdx.x;
    if (i < EE) atomicAdd(&g_cnt[dst[i]], 1);
}

__global__ void scan_kernel() {
    const int T = 1024;
    const int CH = (NN + T - 1) / T;
    __shared__ int ss[T];
    int t = threadIdx.x;
    int lo = t * CH;
    int hi = lo + CH; if (hi > NN) hi = NN;
    int s = 0;
    for (int i = lo; i < hi; i++) s += g_cnt[i];
    ss[t] = s;
    __syncthreads();
    for (int off = 1; off < T; off <<= 1) {
        int v = (t >= off) ? ss[t - off] : 0;
        __syncthreads();
        ss[t] += v;
        __syncthreads();
    }
    int run = (t == 0) ? 0 : ss[t - 1];
    for (int i = lo; i < hi; i++) { g_ptr[i] = run; run += g_cnt[i]; g_cnt[i] = 0; }
    if (t == 0) g_ptr[NN] = ss[T - 1];
}

__global__ void scatter_kernel(const int* __restrict__ src, const int* __restrict__ dst) {
    int i = blockIdx.x * blockDim.x + threadIdx.x;
    if (i < EE) {
        int d = dst[i];
        int off = atomicAdd(&g_cnt[d], 1);
        g_csrc[g_ptr[d] + off] = src[i];
    }
}

__global__ void zero_cnt_kernel() {
    int i = blockIdx.x * blockDim.x + threadIdx.x;
    if (i < NN) g_cnt[i] = 0;
}

// ---------------- row masking ----------------
__global__ void set_rows_kernel(float* __restrict__ buf, const int* __restrict__ idx,
                                int cnt, const float* __restrict__ token) {
    int i = blockIdx.x * blockDim.x + threadIdx.x;
    if (i < cnt * INDIM) {
        int r = idx[i >> 6];
        buf[r * INDIM + (i & 63)] = token[i & 63];
    }
}

// ---------------- decoder remask flags ----------------
__global__ void zero_rflag_kernel() {
    int i = blockIdx.x * blockDim.x + threadIdx.x;
    if (i < NN) g_rflag[i] = 0;
}

__global__ void set_rflag_kernel(const int* __restrict__ remask, int remaskCnt) {
    int i = blockIdx.x * blockDim.x + threadIdx.x;
    if (i < 3 * remaskCnt) {
        int iter = i / remaskCnt;
        atomicOr(&g_rflag[remask[i]], 1 << iter);
    }
}

// ---------------- bf16 split helper: v = hi + lo + O(2^-18 v) ----------------
__device__ __forceinline__ void split_bf16(float v, bf16& h, bf16& l) {
    h = __float2bfloat16_rn(v);
    l = __float2bfloat16_rn(v - __bfloat162float(h));
}

// ---------------- tensor-core GEMM via bf16 3-term split (~fp32 accuracy) ----------------
template <int K, int BN, bool HAS_A2, bool REMASK, bool GUARD>
__global__ __launch_bounds__(256) void gemm_bf16_kernel(
    const float* __restrict__ A, const float* __restrict__ A2, float scaleA,
    const float* __restrict__ W, float* __restrict__ outF,
    const float* __restrict__ token, int iter)
{
    constexpr int BM = 128, KB = 32;
    constexpr int ASTR = KB + 8;
    constexpr int WSTR = BN + 8;
    constexpr int WYC = (BN == 128) ? 2 : 4;
    constexpr int WXC = 8 / WYC;
    constexpr int WM = BM / WYC;
    constexpr int WN = BN / WXC;
    constexpr int AR = WM / 16;
    constexpr int AC = WN / 16;

    constexpr int AS_ELEMS = BM * ASTR;
    constexpr int WS_ELEMS = KB * WSTR;
    constexpr int MAIN_BYTES  = (2 * AS_ELEMS + 2 * WS_ELEMS) * 2;
    constexpr int STAGE_BYTES = GUARD ? BM * BN * 4 : 0;
    constexpr int SM_BYTES    = MAIN_BYTES > STAGE_BYTES ? MAIN_BYTES : STAGE_BYTES;

    __shared__ __align__(32) char sraw[SM_BYTES];
    bf16* AsH = (bf16*)sraw;
    bf16* AsL = AsH + AS_ELEMS;
    bf16* WsH = AsL + AS_ELEMS;
    bf16* WsL = WsH + WS_ELEMS;

    int tid = threadIdx.x;
    int wid = tid >> 5;
    int wy = wid / WXC;
    int wx = wid % WXC;
    long n0 = (long)blockIdx.x * BM;

    wmma::fragment<wmma::accumulator, 16, 16, 16, float> acc[AR][AC];
#pragma unroll
    for (int r = 0; r < AR; r++)
#pragma unroll
        for (int c = 0; c < AC; c++)
            wmma::fill_fragment(acc[r][c], 0.0f);

    for (int kb = 0; kb < K; kb += KB) {
#pragma unroll
        for (int it = 0; it < 4; it++) {
            int f4  = tid + it * 256;
            int row = f4 >> 3;
            int c4  = f4 & 7;
            long n  = n0 + row;
            float4 v = make_float4(0.f, 0.f, 0.f, 0.f);
            if (n < NN) {
                if (REMASK && ((g_rflag[n] >> iter) & 1)) {
                    v = *(const float4*)(token + kb + 4 * c4);
                } else {
                    v = *(const float4*)(A + n * K + kb + 4 * c4);
                    if (HAS_A2) {
                        float4 v2 = *(const float4*)(A2 + n * K + kb + 4 * c4);
                        v.x += v2.x; v.y += v2.y; v.z += v2.z; v.w += v2.w;
                    }
                    v.x *= scaleA; v.y *= scaleA; v.z *= scaleA; v.w *= scaleA;
                }
            }
            bf16 h0, l0, h1, l1, h2, l2, h3, l3;
            split_bf16(v.x, h0, l0);
            split_bf16(v.y, h1, l1);
            split_bf16(v.z, h2, l2);
            split_bf16(v.w, h3, l3);
            int off = row * ASTR + 4 * c4;
            __nv_bfloat162 p;
            p.x = h0; p.y = h1; *(__nv_bfloat162*)&AsH[off]     = p;
            p.x = h2; p.y = h3; *(__nv_bfloat162*)&AsH[off + 2] = p;
            p.x = l0; p.y = l1; *(__nv_bfloat162*)&AsL[off]     = p;
            p.x = l2; p.y = l3; *(__nv_bfloat162*)&AsL[off + 2] = p;
        }
#pragma unroll
        for (int it = 0; it < KB * (BN / 4) / 256; it++) {
            int f4  = tid + it * 256;
            int row = f4 / (BN / 4);
            int c4  = f4 % (BN / 4);
            float4 v = *(const float4*)(W + (long)(kb + row) * BN + 4 * c4);
            bf16 h0, l0, h1, l1, h2, l2, h3, l3;
            split_bf16(v.x, h0, l0);
            split_bf16(v.y, h1, l1);
            split_bf16(v.z, h2, l2);
            split_bf16(v.w, h3, l3);
            int off = row * WSTR + 4 * c4;
            __nv_bfloat162 p;
            p.x = h0; p.y = h1; *(__nv_bfloat162*)&WsH[off]     = p;
            p.x = h2; p.y = h3; *(__nv_bfloat162*)&WsH[off + 2] = p;
            p.x = l0; p.y = l1; *(__nv_bfloat162*)&WsL[off]     = p;
            p.x = l2; p.y = l3; *(__nv_bfloat162*)&WsL[off + 2] = p;
        }
        __syncthreads();

#pragma unroll
        for (int ks = 0; ks < 2; ks++) {
            wmma::fragment<wmma::matrix_b, 16, 16, 16, bf16, wmma::row_major> bH[AC], bL[AC];
#pragma unroll
            for (int c = 0; c < AC; c++) {
                wmma::load_matrix_sync(bH[c], WsH + (ks * 16) * WSTR + wx * WN + c * 16, WSTR);
                wmma::load_matrix_sync(bL[c], WsL + (ks * 16) * WSTR + wx * WN + c * 16, WSTR);
            }
#pragma unroll
            for (int r = 0; r < AR; r++) {
                wmma::fragment<wmma::matrix_a, 16, 16, 16, bf16, wmma::row_major> aH, aL;
                wmma::load_matrix_sync(aH, AsH + (wy * WM + r * 16) * ASTR + ks * 16, ASTR);
                wmma::load_matrix_sync(aL, AsL + (wy * WM + r * 16) * ASTR + ks * 16, ASTR);
#pragma unroll
                for (int c = 0; c < AC; c++) {
                    wmma::mma_sync(acc[r][c], aH, bH[c], acc[r][c]);
                    wmma::mma_sync(acc[r][c], aH, bL[c], acc[r][c]);
                    wmma::mma_sync(acc[r][c], aL, bH[c], acc[r][c]);
                }
            }
        }
        __syncthreads();
    }

    if (!GUARD) {
#pragma unroll
        for (int r = 0; r < AR; r++)
#pragma unroll
            for (int c = 0; c < AC; c++)
                wmma::store_matrix_sync(outF + (n0 + wy * WM + r * 16) * BN + wx * WN + c * 16,
                                        acc[r][c], BN, wmma::mem_row_major);
    } else {
        float* stage = (float*)sraw;
#pragma unroll
        for (int r = 0; r < AR; r++)
#pragma unroll
            for (int c = 0; c < AC; c++)
                wmma::store_matrix_sync(stage + (wy * WM + r * 16) * BN + wx * WN + c * 16,
                                        acc[r][c], BN, wmma::mem_row_major);
        __syncthreads();
#pragma unroll
        for (int it = 0; it < BM * (BN / 4) / 256; it++) {
            int f4  = tid + it * 256;
            int row = f4 / (BN / 4);
            int c4  = f4 % (BN / 4);
            long n  = n0 + row;
            if (n < NN)
                *(float4*)(outF + n * BN + 4 * c4) = *(float4*)(stage + row * BN + 4 * c4);
        }
    }
}

// ---------------- el/er + fp16 shadow: per-node attention logits, feat -> feath ----------------
__global__ __launch_bounds__(256) void elr_kernel(
    const float* __restrict__ feat, const float* __restrict__ al, const float* __restrict__ ar,
    float* __restrict__ el, float* __restrict__ er, __half* __restrict__ feath)
{
    int warp = (blockIdx.x * blockDim.x + threadIdx.x) >> 5;
    if (warp >= NN) return;
    int lane = threadIdx.x & 31;

    float4 f  = *(const float4*)(feat + (long)warp * HDDIM + 4 * lane);

    // fp16 shadow write (8B per lane, coalesced)
    __half2 hlo = __floats2half2_rn(f.x, f.y);
    __half2 hhi = __floats2half2_rn(f.z, f.w);
    uint2 packed;
    packed.x = *(unsigned int*)&hlo;
    packed.y = *(unsigned int*)&hhi;
    *(uint2*)(feath + (long)warp * HDDIM + 4 * lane) = packed;

    float4 a4 = *(const float4*)(al + 4 * lane);
    float4 r4 = *(const float4*)(ar + 4 * lane);
    float ep = f.x * a4.x + f.y * a4.y + f.z * a4.z + f.w * a4.w;
    float rp = f.x * r4.x + f.y * r4.y + f.z * r4.z + f.w * r4.w;
#pragma unroll
    for (int off = 8; off; off >>= 1) {
        ep += __shfl_down_sync(0xffffffffu, ep, off, 16);
        rp += __shfl_down_sync(0xffffffffu, rp, off, 16);
    }
    if ((lane & 15) == 0) {
        el[2 * warp + (lane >> 4)] = ep;
        er[2 * warp + (lane >> 4)] = rp;
    }
}

// ---------------- attention: warp per node; edge softmax + fp16 gather + bias + ELU ----------------
__global__ __launch_bounds__(256) void attn_kernel(
    const __half* __restrict__ feath, const float* __restrict__ el, const float* __restrict__ er,
    const float* __restrict__ bias, float* __restrict__ out, int accumulate)
{
    int warp = (blockIdx.x * blockDim.x + threadIdx.x) >> 5;
    if (warp >= NN) return;
    int lane = threadIdx.x & 31;

    int s = g_ptr[warp], e = g_ptr[warp + 1];
    float er0 = er[2 * warp], er1 = er[2 * warp + 1];

    // pass 1: online softmax stats (fp32 logits)
    float m0 = -1e30f, m1 = -1e30f, s0 = 0.f, s1 = 0.f;
    for (int i = s + lane; i < e; i += 32) {
        int sv = g_csrc[i];
        float2 ev = *(const float2*)(el + 2 * sv);
        float e0 = ev.x + er0; e0 = (e0 > 0.f) ? e0 : 0.2f * e0;
        float e1 = ev.y + er1; e1 = (e1 > 0.f) ? e1 : 0.2f * e1;
        float nm0 = fmaxf(m0, e0);
        s0 = s0 * __expf(m0 - nm0) + __expf(e0 - nm0);
        m0 = nm0;
        float nm1 = fmaxf(m1, e1);
        s1 = s1 * __expf(m1 - nm1) + __expf(e1 - nm1);
        m1 = nm1;
    }
#pragma unroll
    for (int off = 16; off; off >>= 1) {
        float om0 = __shfl_down_sync(0xffffffffu, m0, off);
        float os0 = __shfl_down_sync(0xffffffffu, s0, off);
        float nm0 = fmaxf(m0, om0);
        s0 = s0 * __expf(m0 - nm0) + os0 * __expf(om0 - nm0);
        m0 = nm0;
        float om1 = __shfl_down_sync(0xffffffffu, m1, off);
        float os1 = __shfl_down_sync(0xffffffffu, s1, off);
        float nm1 = fmaxf(m1, om1);
        s1 = s1 * __expf(m1 - nm1) + os1 * __expf(om1 - nm1);
        m1 = nm1;
    }
    m0 = __shfl_sync(0xffffffffu, m0, 0);
    s0 = __shfl_sync(0xffffffffu, s0, 0);
    m1 = __shfl_sync(0xffffffffu, m1, 0);
    s1 = __shfl_sync(0xffffffffu, s1, 0);
    float inv0 = 1.f / s0, inv1 = 1.f / s1;

    // pass 2: weighted gather from fp16 shadow (256B/edge)
    int colbase = 4 * lane;
    const bool head0 = (colbase < 64);
    const __half* feathc = feath + colbase;
    float4 acc = make_float4(0.f, 0.f, 0.f, 0.f);
    for (int base = s; base < e; base += 32) {
        int i = base + lane;
        float a0 = 0.f, a1 = 0.f;
        int sv = 0;
        if (i < e) {
            sv = g_csrc[i];
            float2 ev = *(const float2*)(el + 2 * sv);
            float e0 = ev.x + er0; e0 = (e0 > 0.f) ? e0 : 0.2f * e0;
            float e1 = ev.y + er1; e1 = (e1 > 0.f) ? e1 : 0.2f * e1;
            a0 = __expf(e0 - m0) * inv0;
            a1 = __expf(e1 - m1) * inv1;
        }
        int cnt = e - base; if (cnt > 32) cnt = 32;
        for (int j = 0; j < cnt; j++) {
            int sj = __shfl_sync(0xffffffffu, sv, j);
            float q0 = __shfl_sync(0xffffffffu, a0, j);
            float q1 = __shfl_sync(0xffffffffu, a1, j);
            float wj = head0 ? q0 : q1;
            uint2 hraw = *(const uint2*)(feathc + (long)sj * HDDIM);
            float2 f01 = __half22float2(*(__half2*)&hraw.x);
            float2 f23 = __half22float2(*(__half2*)&hraw.y);
            acc.x += wj * f01.x;
            acc.y += wj * f01.y;
            acc.z += wj * f23.x;
            acc.w += wj * f23.y;
        }
    }

    float4 bv = *(const float4*)(bias + colbase);
    float4 v;
    v.x = acc.x + bv.x; v.x = (v.x > 0.f) ? v.x : expm1f(v.x);
    v.y = acc.y + bv.y; v.y = (v.y > 0.f) ? v.y : expm1f(v.y);
    v.z = acc.z + bv.z; v.z = (v.z > 0.f) ? v.z : expm1f(v.z);
    v.w = acc.w + bv.w; v.w = (v.w > 0.f) ? v.w : expm1f(v.w);

    float* o = out + (long)warp * HDDIM + colbase;
    if (accumulate) {
        float4 p = *(const float4*)o;
        v.x += p.x; v.y += p.y; v.z += p.z; v.w += p.w;
    }
    *(float4*)o = v;
}

// ---------------- host ----------------
extern "C" void kernel_launch(void* const* d_in, const int* in_sizes, int n_in,
                              void* d_out, int out_size)
{
    const float* x        = (const float*)d_in[0];
    const int*   src      = (const int*)d_in[1];
    const int*   dst      = (const int*)d_in[2];
    const int*   encm     = (const int*)d_in[3];
    const int*   remask   = (const int*)d_in[4];
    const float* enc_fc0  = (const float*)d_in[5];
    const float* enc_al0  = (const float*)d_in[6];
    const float* enc_ar0  = (const float*)d_in[7];
    const float* enc_b0   = (const float*)d_in[8];
    const float* enc_fc1  = (const float*)d_in[9];
    const float* enc_al1  = (const float*)d_in[10];
    const float* enc_ar1  = (const float*)d_in[11];
    const float* enc_b1   = (const float*)d_in[12];
    const float* dec_fc0  = (const float*)d_in[13];
    const float* dec_al0  = (const float*)d_in[14];
    const float* dec_ar0  = (const float*)d_in[15];
    const float* dec_b0   = (const float*)d_in[16];
    const float* dec_fc1  = (const float*)d_in[17];
    const float* dec_al1  = (const float*)d_in[18];
    const float* dec_ar1  = (const float*)d_in[19];
    const float* dec_b1   = (const float*)d_in[20];
    const float* enc_tok  = (const float*)d_in[21];
    const float* dec_tok  = (const float*)d_in[22];
    const float* W_e2d    = (const float*)d_in[23];
    const float* W_d2c    = (const float*)d_in[24];
    float* out = (float*)d_out;

    int encCnt    = in_sizes[3];
    int remaskCnt = in_sizes[4] / 3;

    void *p_maskx, *p_feat, *p_feath, *p_el, *p_er, *p_h0, *p_h1, *p_rep0, *p_r0, *p_acc;
    cudaGetSymbolAddress(&p_maskx, g_maskx);
    cudaGetSymbolAddress(&p_feat,  g_feat);
    cudaGetSymbolAddress(&p_feath, g_feath);
    cudaGetSymbolAddress(&p_el,    g_el);
    cudaGetSymbolAddress(&p_er,    g_er);
    cudaGetSymbolAddress(&p_h0,    g_h0);
    cudaGetSymbolAddress(&p_h1,    g_h1);
    cudaGetSymbolAddress(&p_rep0,  g_rep0);
    cudaGetSymbolAddress(&p_r0,    g_r0);
    cudaGetSymbolAddress(&p_acc,   g_accb);

    float*  maskx = (float*)p_maskx;
    float*  feat  = (float*)p_feat;
    __half* feath = (__half*)p_feath;
    float*  el    = (float*)p_el;
    float*  er    = (float*)p_er;
    float*  h0    = (float*)p_h0;
    float*  h1    = (float*)p_h1;
    float*  rep0  = (float*)p_rep0;
    float*  r0    = (float*)p_r0;
    float*  accb  = (float*)p_acc;

    const int EB  = (EE + 255) / 256;
    const int GTC = NNPAD / 128;
    const int AB  = (NN + 7) / 8;

    // ---- CSR build ----
    hist_kernel<<<EB, 256>>>(dst);
    scan_kernel<<<1, 1024>>>();
    scatter_kernel<<<EB, 256>>>(src, dst);

    // ---- encoder mask ----
    cudaMemcpyAsync(maskx, x, (size_t)NN * INDIM * sizeof(float), cudaMemcpyDeviceToDevice);
    set_rows_kernel<<<(encCnt * INDIM + 255) / 256, 256>>>(maskx, encm, encCnt, enc_tok);

    // ---- decoder remask flags ----
    zero_rflag_kernel<<<(NN + 255) / 256, 256>>>();
    set_rflag_kernel<<<(3 * remaskCnt + 255) / 256, 256>>>(remask, remaskCnt);

    // ---- encoder layer 0 ----
    gemm_bf16_kernel<INDIM, HDDIM, false, false, false><<<GTC, 256>>>(
        maskx, nullptr, 1.f, enc_fc0, feat, nullptr, 0);
    elr_kernel<<<AB, 256>>>(feat, enc_al0, enc_ar0, el, er, feath);
    attn_kernel<<<AB, 256>>>(feath, el, er, enc_b0, h0, 0);

    // ---- encoder layer 1 ----
    gemm_bf16_kernel<HDDIM, HDDIM, false, false, false><<<GTC, 256>>>(
        h0, nullptr, 1.f, enc_fc1, feat, nullptr, 0);
    elr_kernel<<<AB, 256>>>(feat, enc_al1, enc_ar1, el, er, feath);
    attn_kernel<<<AB, 256>>>(feath, el, er, enc_b1, h1, 0);

    // ---- Es = 0.5*(h0+h1); origin_rep = Es @ W_e2d ----
    gemm_bf16_kernel<HDDIM, INDIM, true, false, false><<<GTC, 256>>>(
        h0, h1, 0.5f, W_e2d, rep0, nullptr, 0);

    // ---- decoder x3, accumulate r1 into accb ----
    cudaMemsetAsync(p_acc, 0, (size_t)NN * HDDIM * sizeof(float));
    for (int i = 0; i < 3; i++) {
        gemm_bf16_kernel<INDIM, HDDIM, false, true, false><<<GTC, 256>>>(
            rep0, nullptr, 1.f, dec_fc0, feat, dec_tok, i);
        elr_kernel<<<AB, 256>>>(feat, dec_al0, dec_ar0, el, er, feath);
        attn_kernel<<<AB, 256>>>(feath, el, er, dec_b0, r0, 0);

        gemm_bf16_kernel<HDDIM, HDDIM, false, false, false><<<GTC, 256>>>(
            r0, nullptr, 1.f, dec_fc1, feat, nullptr, 0);
        elr_kernel<<<AB, 256>>>(feat, dec_al1, dec_ar1, el, er, feath);
        attn_kernel<<<AB, 256>>>(feath, el, er, dec_b1, accb, 1);
    }

    // ---- out = (accb/3) @ W_d2c ----
    gemm_bf16_kernel<HDDIM, INDIM, false, false, true><<<GTC, 256>>>(
        accb, nullptr, 1.f / 3.f, W_d2c, out, nullptr, 0);

    // ---- leave g_cnt zero for the next call ----
    zero_cnt_kernel<<<(NN + 255) / 256, 256>>>();
}